// round 1
// baseline (speedup 1.0000x reference)
#include <cuda_runtime.h>

// Problem constants (fixed by setup_inputs)
#define B_SZ   2
#define S_LEN  2048
#define D_DIM  2048
#define L_DIM  512
#define NHEADS 16
#define HDIM   128
#define WIN    128
#define SINK   16
#define MROWS  (B_SZ * S_LEN)   // 4096

// ---------------- scratch (device globals; no runtime allocation) ------------
__device__ float g_Q [MROWS * D_DIM];
__device__ float g_KV[MROWS * L_DIM];
__device__ float g_K [MROWS * D_DIM];
__device__ float g_V [MROWS * D_DIM];
__device__ float g_AO[MROWS * D_DIM];

// ---------------- fp32 SGEMM: C[M,N] = A[M,K] @ B[K,N], row-major ------------
#define GBM 128
#define GBN 128
#define GBK 8
#define GTM 8
#define GTN 8

__global__ __launch_bounds__(256) void sgemm_kernel(
    const float* __restrict__ A, const float* __restrict__ B,
    float* __restrict__ C, int M, int N, int K)
{
    __shared__ float As[GBK][GBM];   // A tile transposed
    __shared__ float Bs[GBK][GBN];

    const int tid = threadIdx.x;
    const int bn = blockIdx.x, bm = blockIdx.y;
    const int ty = tid >> 4;          // 0..15
    const int tx = tid & 15;          // 0..15
    const int arow = tid >> 1;        // 0..127
    const int acol = (tid & 1) << 2;  // 0 or 4
    const int brow = tid >> 5;        // 0..7
    const int bcol = (tid & 31) << 2; // 0..124

    const float* Ag = A + (size_t)(bm * GBM + arow) * K + acol;
    const float* Bg = B + (size_t)brow * N + bn * GBN + bcol;

    float acc[GTM][GTN];
#pragma unroll
    for (int i = 0; i < GTM; i++)
#pragma unroll
        for (int j = 0; j < GTN; j++) acc[i][j] = 0.0f;

    for (int k0 = 0; k0 < K; k0 += GBK) {
        float4 a4 = *(const float4*)(Ag + k0);
        As[acol + 0][arow] = a4.x;
        As[acol + 1][arow] = a4.y;
        As[acol + 2][arow] = a4.z;
        As[acol + 3][arow] = a4.w;
        float4 b4 = *(const float4*)(Bg + (size_t)k0 * N);
        *(float4*)(&Bs[brow][bcol]) = b4;
        __syncthreads();

#pragma unroll
        for (int k = 0; k < GBK; k++) {
            float a[GTM], b[GTN];
#pragma unroll
            for (int i = 0; i < GTM; i++) a[i] = As[k][ty * GTM + i];
#pragma unroll
            for (int j = 0; j < GTN; j++) b[j] = Bs[k][tx * GTN + j];
#pragma unroll
            for (int i = 0; i < GTM; i++)
#pragma unroll
                for (int j = 0; j < GTN; j++)
                    acc[i][j] = fmaf(a[i], b[j], acc[i][j]);
        }
        __syncthreads();
    }

    float* Cg = C + (size_t)(bm * GBM + ty * GTM) * N + bn * GBN + tx * GTN;
#pragma unroll
    for (int i = 0; i < GTM; i++) {
        float4 c0 = make_float4(acc[i][0], acc[i][1], acc[i][2], acc[i][3]);
        float4 c1 = make_float4(acc[i][4], acc[i][5], acc[i][6], acc[i][7]);
        *(float4*)(Cg + (size_t)i * N)     = c0;
        *(float4*)(Cg + (size_t)i * N + 4) = c1;
    }
}

// ---------------- fused sliding-window + sink attention ----------------------
// One block = 64 queries of one (b,h). Key tiles: {0 (covers sinks)} union
// window tiles. Online softmax, fp32.
#define QT 64
#define KT 64
#define QP 132   // Q smem pitch (float4-aligned)
#define KP 129   // K smem pitch (odd -> conflict-free strided-key reads)
#define VP 128   // V smem pitch
#define PP 64    // P smem pitch

#define ATTN_SMEM_FLOATS (QT*QP + KT*KP + KT*VP + QT*PP)
#define ATTN_SMEM_BYTES  (ATTN_SMEM_FLOATS * 4)

__global__ __launch_bounds__(256, 1) void attn_kernel(
    const float* __restrict__ Q, const float* __restrict__ K,
    const float* __restrict__ V, float* __restrict__ O)
{
    extern __shared__ float sm[];
    float* Qs = sm;                 // [QT][QP]
    float* Ks = Qs + QT * QP;       // [KT][KP]
    float* Vs = Ks + KT * KP;       // [KT][VP]
    float* Ps = Vs + KT * VP;       // [QT][PP]

    const int tid = threadIdx.x;
    const int ty = tid >> 4;        // 0..15  -> q rows ty*4..ty*4+3
    const int tx = tid & 15;        // 0..15  -> keys kj*16+tx, dims j*16+tx
    const int b = blockIdx.z, h = blockIdx.y;
    const int q0 = blockIdx.x * QT;
    const float scale = 0.08838834764831845f;   // 1/sqrt(128)

    // load Q tile (64 x 128)
    const float* Qg = Q + ((size_t)(b * S_LEN + q0)) * D_DIM + h * HDIM;
#pragma unroll
    for (int i = 0; i < 8; i++) {
        int idx = tid + i * 256;
        int r = idx >> 5, c = (idx & 31) << 2;
        float4 v4 = *(const float4*)(Qg + (size_t)r * D_DIM + c);
        *(float4*)(Qs + r * QP + c) = v4;
    }

    float m_run[4], l_run[4], acc[4][8];
#pragma unroll
    for (int i = 0; i < 4; i++) {
        m_run[i] = -1e30f; l_run[i] = 0.0f;
#pragma unroll
        for (int j = 0; j < 8; j++) acc[i][j] = 0.0f;
    }

    const int lastTile = q0 >> 6;
    int wstart = (q0 >= WIN) ? ((q0 - (WIN - 1)) >> 6) : 0;
    if (wstart < 1) wstart = 1;

    for (int kt = 0; kt <= lastTile; kt++) {
        if (kt != 0 && kt < wstart) continue;   // block-uniform skip
        const int kb = kt * KT;

        __syncthreads();   // previous AV done (and Q load visible on 1st iter)
        const float* Kg = K + ((size_t)(b * S_LEN + kb)) * D_DIM + h * HDIM;
        const float* Vg = V + ((size_t)(b * S_LEN + kb)) * D_DIM + h * HDIM;
#pragma unroll
        for (int i = 0; i < 8; i++) {
            int idx = tid + i * 256;
            int r = idx >> 5, c = (idx & 31) << 2;
            float4 k4 = *(const float4*)(Kg + (size_t)r * D_DIM + c);
            Ks[r * KP + c + 0] = k4.x;
            Ks[r * KP + c + 1] = k4.y;
            Ks[r * KP + c + 2] = k4.z;
            Ks[r * KP + c + 3] = k4.w;
            float4 v4 = *(const float4*)(Vg + (size_t)r * D_DIM + c);
            *(float4*)(Vs + r * VP + c) = v4;
        }
        __syncthreads();

        // scores S[4q][4k], key local index = kj*16 + tx
        float s[4][4];
#pragma unroll
        for (int qi = 0; qi < 4; qi++)
#pragma unroll
            for (int kj = 0; kj < 4; kj++) s[qi][kj] = 0.0f;

        for (int d = 0; d < HDIM; d++) {
            float a[4], bb[4];
#pragma unroll
            for (int qi = 0; qi < 4; qi++) a[qi] = Qs[(ty * 4 + qi) * QP + d];
#pragma unroll
            for (int kj = 0; kj < 4; kj++) bb[kj] = Ks[(kj * 16 + tx) * KP + d];
#pragma unroll
            for (int qi = 0; qi < 4; qi++)
#pragma unroll
                for (int kj = 0; kj < 4; kj++)
                    s[qi][kj] = fmaf(a[qi], bb[kj], s[qi][kj]);
        }

        // mask + scale
#pragma unroll
        for (int qi = 0; qi < 4; qi++) {
            const int qg = q0 + ty * 4 + qi;
#pragma unroll
            for (int kj = 0; kj < 4; kj++) {
                const int kg = kb + kj * 16 + tx;
                const bool valid =
                    (kg <= qg) && ((qg - kg < WIN) || (kg < SINK));
                s[qi][kj] = valid ? s[qi][kj] * scale : -1e30f;
            }
        }

        // online softmax update (reduce across the 16 tx lanes of each half-warp)
#pragma unroll
        for (int qi = 0; qi < 4; qi++) {
            float tm = fmaxf(fmaxf(s[qi][0], s[qi][1]), fmaxf(s[qi][2], s[qi][3]));
#pragma unroll
            for (int o = 1; o < 16; o <<= 1)
                tm = fmaxf(tm, __shfl_xor_sync(0xffffffffu, tm, o));
            const float m_new = fmaxf(m_run[qi], tm);
            const float p0 = __expf(s[qi][0] - m_new);
            const float p1 = __expf(s[qi][1] - m_new);
            const float p2 = __expf(s[qi][2] - m_new);
            const float p3 = __expf(s[qi][3] - m_new);
            float rs = p0 + p1 + p2 + p3;
#pragma unroll
            for (int o = 1; o < 16; o <<= 1)
                rs += __shfl_xor_sync(0xffffffffu, rs, o);
            const float alpha = __expf(m_run[qi] - m_new);
            l_run[qi] = l_run[qi] * alpha + rs;
            m_run[qi] = m_new;
#pragma unroll
            for (int j = 0; j < 8; j++) acc[qi][j] *= alpha;
            Ps[(ty * 4 + qi) * PP + 0 * 16 + tx] = p0;
            Ps[(ty * 4 + qi) * PP + 1 * 16 + tx] = p1;
            Ps[(ty * 4 + qi) * PP + 2 * 16 + tx] = p2;
            Ps[(ty * 4 + qi) * PP + 3 * 16 + tx] = p3;
        }
        __syncthreads();

        // O += P @ V   (dims owned by this thread: j*16 + tx)
        for (int kk = 0; kk < KT; kk++) {
            float vv[8];
#pragma unroll
            for (int j = 0; j < 8; j++) vv[j] = Vs[kk * VP + j * 16 + tx];
#pragma unroll
            for (int qi = 0; qi < 4; qi++) {
                const float p = Ps[(ty * 4 + qi) * PP + kk];
#pragma unroll
                for (int j = 0; j < 8; j++)
                    acc[qi][j] = fmaf(p, vv[j], acc[qi][j]);
            }
        }
    }

    // normalize + write
    float* Og = O + ((size_t)(b * S_LEN + q0 + ty * 4)) * D_DIM + h * HDIM;
#pragma unroll
    for (int qi = 0; qi < 4; qi++) {
        const float inv = 1.0f / l_run[qi];
#pragma unroll
        for (int j = 0; j < 8; j++)
            Og[(size_t)qi * D_DIM + j * 16 + tx] = acc[qi][j] * inv;
    }
}

// ---------------- launch ------------------------------------------------------
extern "C" void kernel_launch(void* const* d_in, const int* in_sizes, int n_in,
                              void* d_out, int out_size)
{
    const float* x   = (const float*)d_in[0];
    const float* Wq  = (const float*)d_in[1];
    const float* Wkv = (const float*)d_in[2];
    const float* Wk  = (const float*)d_in[3];
    const float* Wv  = (const float*)d_in[4];
    const float* Wo  = (const float*)d_in[5];
    float* out = (float*)d_out;

    float *Q, *KV, *K, *V, *AO;
    cudaGetSymbolAddress((void**)&Q,  g_Q);
    cudaGetSymbolAddress((void**)&KV, g_KV);
    cudaGetSymbolAddress((void**)&K,  g_K);
    cudaGetSymbolAddress((void**)&V,  g_V);
    cudaGetSymbolAddress((void**)&AO, g_AO);

    const dim3 blk(256);
    // Q = X @ Wq
    sgemm_kernel<<<dim3(D_DIM / GBN, MROWS / GBM), blk>>>(x, Wq, Q, MROWS, D_DIM, D_DIM);
    // KV = X @ Wkv
    sgemm_kernel<<<dim3(L_DIM / GBN, MROWS / GBM), blk>>>(x, Wkv, KV, MROWS, L_DIM, D_DIM);
    // K = KV @ Wk
    sgemm_kernel<<<dim3(D_DIM / GBN, MROWS / GBM), blk>>>(KV, Wk, K, MROWS, D_DIM, L_DIM);
    // V = KV @ Wv
    sgemm_kernel<<<dim3(D_DIM / GBN, MROWS / GBM), blk>>>(KV, Wv, V, MROWS, D_DIM, L_DIM);

    // attention
    cudaFuncSetAttribute(attn_kernel,
                         cudaFuncAttributeMaxDynamicSharedMemorySize,
                         ATTN_SMEM_BYTES);
    attn_kernel<<<dim3(S_LEN / QT, NHEADS, B_SZ), blk, ATTN_SMEM_BYTES>>>(Q, K, V, AO);

    // OUT = AO @ Wo
    sgemm_kernel<<<dim3(D_DIM / GBN, MROWS / GBM), blk>>>(AO, Wo, out, MROWS, D_DIM, D_DIM);
}

// round 3
// speedup vs baseline: 2.8975x; 2.8975x over previous
#include <cuda_runtime.h>
#include <cuda_bf16.h>
#include <cstdint>

// ---------------- problem constants ----------------
#define B_SZ   2
#define S_LEN  2048
#define D_DIM  2048
#define L_DIM  512
#define NHEADS 16
#define HDIM   128
#define WIN    128
#define SINK   16
#define MROWS  (B_SZ * S_LEN)   // 4096

// ---------------- PTX helpers (base sm_103 ISA only) ----------------
__device__ __forceinline__ uint32_t smem_to_u32(const void* p) {
    uint32_t a;
    asm("{ .reg .u64 t; cvta.to.shared.u64 t, %1; cvt.u32.u64 %0, t; }" : "=r"(a) : "l"(p));
    return a;
}

#define CP_ASYNC16(saddr, gaddr) \
    asm volatile("cp.async.cg.shared.global [%0], [%1], 16;" :: "r"(saddr), "l"(gaddr) : "memory")
#define CP_COMMIT()  asm volatile("cp.async.commit_group;" ::: "memory")
#define CP_WAIT1()   asm volatile("cp.async.wait_group 1;" ::: "memory")
#define CP_WAIT0()   asm volatile("cp.async.wait_group 0;" ::: "memory")

#define LDSM4(r, addr) \
    asm volatile("ldmatrix.sync.aligned.m8n8.x4.shared.b16 {%0,%1,%2,%3}, [%4];" \
        : "=r"((r)[0]), "=r"((r)[1]), "=r"((r)[2]), "=r"((r)[3]) : "r"(addr))

#define MMA16816(d, a, b0, b1) \
    asm volatile("mma.sync.aligned.m16n8k16.row.col.f32.bf16.bf16.f32 " \
        "{%0,%1,%2,%3},{%4,%5,%6,%7},{%8,%9},{%0,%1,%2,%3};" \
        : "+f"((d)[0]), "+f"((d)[1]), "+f"((d)[2]), "+f"((d)[3]) \
        : "r"((a)[0]), "r"((a)[1]), "r"((a)[2]), "r"((a)[3]), "r"(b0), "r"(b1))

// ---------------- scratch (device globals) ----------------
__device__ float g_Q [MROWS * D_DIM];
__device__ float g_K [MROWS * D_DIM];
__device__ float g_V [MROWS * D_DIM];

__device__ __nv_bfloat16 g_Xh  [MROWS * D_DIM];
__device__ __nv_bfloat16 g_Xl  [MROWS * D_DIM];
__device__ __nv_bfloat16 g_KVh [MROWS * L_DIM];
__device__ __nv_bfloat16 g_KVl [MROWS * L_DIM];
__device__ __nv_bfloat16 g_AOh [MROWS * D_DIM];
__device__ __nv_bfloat16 g_AOl [MROWS * D_DIM];
// transposed weights [N, K] (hi/lo bf16 splits)
__device__ __nv_bfloat16 g_WqTh [D_DIM * D_DIM];
__device__ __nv_bfloat16 g_WqTl [D_DIM * D_DIM];
__device__ __nv_bfloat16 g_WkvTh[L_DIM * D_DIM];
__device__ __nv_bfloat16 g_WkvTl[L_DIM * D_DIM];
__device__ __nv_bfloat16 g_WkTh [D_DIM * L_DIM];
__device__ __nv_bfloat16 g_WkTl [D_DIM * L_DIM];
__device__ __nv_bfloat16 g_WvTh [D_DIM * L_DIM];
__device__ __nv_bfloat16 g_WvTl [D_DIM * L_DIM];
__device__ __nv_bfloat16 g_WoTh [D_DIM * D_DIM];
__device__ __nv_bfloat16 g_WoTl [D_DIM * D_DIM];

// ---------------- split conversions ----------------
__global__ void split_kernel(const float4* __restrict__ in,
                             __nv_bfloat162* __restrict__ hi,
                             __nv_bfloat162* __restrict__ lo, int n4)
{
    int i = blockIdx.x * blockDim.x + threadIdx.x;
    if (i >= n4) return;
    float4 v = in[i];
    __nv_bfloat16 h0 = __float2bfloat16(v.x);
    __nv_bfloat16 h1 = __float2bfloat16(v.y);
    __nv_bfloat16 h2 = __float2bfloat16(v.z);
    __nv_bfloat16 h3 = __float2bfloat16(v.w);
    __nv_bfloat16 l0 = __float2bfloat16(v.x - __bfloat162float(h0));
    __nv_bfloat16 l1 = __float2bfloat16(v.y - __bfloat162float(h1));
    __nv_bfloat16 l2 = __float2bfloat16(v.z - __bfloat162float(h2));
    __nv_bfloat16 l3 = __float2bfloat16(v.w - __bfloat162float(h3));
    __nv_bfloat162 a, b, c, d;
    a.x = h0; a.y = h1; b.x = h2; b.y = h3;
    c.x = l0; c.y = l1; d.x = l2; d.y = l3;
    hi[2 * i] = a; hi[2 * i + 1] = b;
    lo[2 * i] = c; lo[2 * i + 1] = d;
}

// in [K, N] fp32 -> out [N, K] bf16 (hi/lo)
__global__ void tsplit_kernel(const float* __restrict__ in,
                              __nv_bfloat16* __restrict__ hi,
                              __nv_bfloat16* __restrict__ lo,
                              int K, int N)
{
    __shared__ float tile[32][33];
    int kb = blockIdx.y * 32, nb = blockIdx.x * 32;
    int tx = threadIdx.x, ty = threadIdx.y;
#pragma unroll
    for (int j = 0; j < 32; j += 8)
        tile[ty + j][tx] = in[(size_t)(kb + ty + j) * N + nb + tx];
    __syncthreads();
#pragma unroll
    for (int j = 0; j < 32; j += 8) {
        float v = tile[tx][ty + j];
        __nv_bfloat16 h = __float2bfloat16(v);
        __nv_bfloat16 l = __float2bfloat16(v - __bfloat162float(h));
        size_t o = (size_t)(nb + ty + j) * K + kb + tx;
        hi[o] = h; lo[o] = l;
    }
}

// ---------------- bf16-split HMMA GEMM ----------------------------------------
// C[M,N] = A[M,K] @ B^T where B stored [N,K]. C = Ah*Bh + Ah*Bl + Al*Bh (fp32 acc).
// 128x128 CTA tile, BK=64, 8 warps (2x4), warp tile 64x32, double-buffered cp.async.
#define MM_STAGE_BYTES 65536   // 4 tiles * 128 rows * 128B
#define MM_SMEM_BYTES  (2 * MM_STAGE_BYTES)

__device__ __forceinline__ void mm_load_chunk(
    uint32_t sb, int ck, int tid,
    const __nv_bfloat16* __restrict__ Ah, const __nv_bfloat16* __restrict__ Al,
    const __nv_bfloat16* __restrict__ Bh, const __nv_bfloat16* __restrict__ Bl,
    int m0, int n0, int K)
{
    const int k0 = ck * 64;
#pragma unroll
    for (int it = 0; it < 4; it++) {
        int idx = tid + it * 256;      // 0..1023
        int r   = idx >> 3;            // 0..127
        int cb  = (idx & 7) << 4;      // 16B unit -> byte col
        uint32_t off = (uint32_t)(r * 128 + cb);
        uint32_t sw  = off ^ ((off >> 3) & 0x70);
        const char* pa  = (const char*)(Ah + (size_t)(m0 + r) * K + k0) + cb;
        const char* pal = (const char*)(Al + (size_t)(m0 + r) * K + k0) + cb;
        const char* pb  = (const char*)(Bh + (size_t)(n0 + r) * K + k0) + cb;
        const char* pbl = (const char*)(Bl + (size_t)(n0 + r) * K + k0) + cb;
        CP_ASYNC16(sb + sw,          pa);
        CP_ASYNC16(sb + 16384u + sw, pal);
        CP_ASYNC16(sb + 32768u + sw, pb);
        CP_ASYNC16(sb + 49152u + sw, pbl);
    }
}

__global__ __launch_bounds__(256, 1)
void mm_kernel(const __nv_bfloat16* __restrict__ Ah,
               const __nv_bfloat16* __restrict__ Al,
               const __nv_bfloat16* __restrict__ Bh,
               const __nv_bfloat16* __restrict__ Bl,
               float* __restrict__ C,
               __nv_bfloat16* __restrict__ Oh,   // used when split_out != 0
               __nv_bfloat16* __restrict__ Ol,
               int N, int K, int split_out)
{
    extern __shared__ __align__(1024) char dsm[];
    const uint32_t smem = smem_to_u32(dsm);

    const int tid  = threadIdx.x;
    const int wid  = tid >> 5;
    const int lane = tid & 31;
    const int warp_m = wid & 1;          // 0..1  -> 64 rows
    const int warp_n = wid >> 1;         // 0..3  -> 32 cols
    const int m0 = blockIdx.y * 128, n0 = blockIdx.x * 128;

    float d[4][4][4];
#pragma unroll
    for (int mt = 0; mt < 4; mt++)
#pragma unroll
        for (int nt = 0; nt < 4; nt++)
#pragma unroll
            for (int j = 0; j < 4; j++) d[mt][nt][j] = 0.0f;

    const int nch = K / 64;
    mm_load_chunk(smem, 0, tid, Ah, Al, Bh, Bl, m0, n0, K);
    CP_COMMIT();

    // per-lane ldmatrix address components
    const int a_row  = warp_m * 64 + (lane & 15);
    const int a_kofs = (lane >> 4) << 4;                         // bytes
    const int b_row  = warp_n * 32 + ((lane >> 4) << 3) + (lane & 7);
    const int b_kofs = ((lane >> 3) & 1) << 4;                   // bytes

    for (int i = 0; i < nch; i++) {
        if (i + 1 < nch) {
            mm_load_chunk(smem + ((i + 1) & 1) * MM_STAGE_BYTES, i + 1, tid,
                          Ah, Al, Bh, Bl, m0, n0, K);
            CP_COMMIT();
            CP_WAIT1();
        } else {
            CP_WAIT0();
        }
        __syncthreads();

        const uint32_t sb = smem + (i & 1) * MM_STAGE_BYTES;
#pragma unroll
        for (int ks = 0; ks < 4; ks++) {
            const int kb = ks * 32;   // byte offset of k-step within 128B row
            uint32_t ah[4][4], al[4][4], bh[2][4], bl[2][4];
#pragma unroll
            for (int mt = 0; mt < 4; mt++) {
                uint32_t off = (uint32_t)((a_row + mt * 16) * 128 + kb + a_kofs);
                uint32_t sw  = off ^ ((off >> 3) & 0x70);
                LDSM4(ah[mt], sb + sw);
                LDSM4(al[mt], sb + 16384u + sw);
            }
#pragma unroll
            for (int np = 0; np < 2; np++) {
                uint32_t off = (uint32_t)((b_row + np * 16) * 128 + kb + b_kofs);
                uint32_t sw  = off ^ ((off >> 3) & 0x70);
                LDSM4(bh[np], sb + 32768u + sw);
                LDSM4(bl[np], sb + 49152u + sw);
            }
#pragma unroll
            for (int mt = 0; mt < 4; mt++) {
#pragma unroll
                for (int nt = 0; nt < 4; nt++) {
                    const int np = nt >> 1, h = (nt & 1) << 1;
                    MMA16816(d[mt][nt], ah[mt], bh[np][h], bh[np][h + 1]);
                    MMA16816(d[mt][nt], ah[mt], bl[np][h], bl[np][h + 1]);
                    MMA16816(d[mt][nt], al[mt], bh[np][h], bh[np][h + 1]);
                }
            }
        }
        __syncthreads();
    }

    // epilogue
    const int gid = lane >> 2, tig = lane & 3;
    const int mbase = m0 + warp_m * 64 + gid;
    const int nbase = n0 + warp_n * 32 + tig * 2;
    if (!split_out) {
#pragma unroll
        for (int mt = 0; mt < 4; mt++)
#pragma unroll
            for (int nt = 0; nt < 4; nt++) {
                const int m = mbase + mt * 16;
                const int n = nbase + nt * 8;
                *(float2*)(C + (size_t)m * N + n)       = make_float2(d[mt][nt][0], d[mt][nt][1]);
                *(float2*)(C + (size_t)(m + 8) * N + n) = make_float2(d[mt][nt][2], d[mt][nt][3]);
            }
    } else {
#pragma unroll
        for (int mt = 0; mt < 4; mt++)
#pragma unroll
            for (int nt = 0; nt < 4; nt++) {
#pragma unroll
                for (int half = 0; half < 2; half++) {
                    const int m = mbase + mt * 16 + half * 8;
                    const int n = nbase + nt * 8;
                    float v0 = d[mt][nt][half * 2], v1 = d[mt][nt][half * 2 + 1];
                    __nv_bfloat16 h0 = __float2bfloat16(v0);
                    __nv_bfloat16 h1 = __float2bfloat16(v1);
                    __nv_bfloat162 hh, ll;
                    hh.x = h0; hh.y = h1;
                    ll.x = __float2bfloat16(v0 - __bfloat162float(h0));
                    ll.y = __float2bfloat16(v1 - __bfloat162float(h1));
                    *(__nv_bfloat162*)(Oh + (size_t)m * N + n) = hh;
                    *(__nv_bfloat162*)(Ol + (size_t)m * N + n) = ll;
                }
            }
    }
}

// ---------------- fused sliding-window + sink attention ----------------------
// Writes AO directly as bf16 hi/lo splits for the final GEMM.
#define QT 64
#define KT 64
#define QP 132
#define KP 129
#define VP 128
#define PP 64
#define ATTN_SMEM_FLOATS (QT*QP + KT*KP + KT*VP + QT*PP)
#define ATTN_SMEM_BYTES  (ATTN_SMEM_FLOATS * 4)

__global__ __launch_bounds__(256, 1) void attn_kernel(
    const float* __restrict__ Q, const float* __restrict__ K,
    const float* __restrict__ V,
    __nv_bfloat16* __restrict__ Oh, __nv_bfloat16* __restrict__ Ol)
{
    extern __shared__ float sm[];
    float* Qs = sm;
    float* Ks = Qs + QT * QP;
    float* Vs = Ks + KT * KP;
    float* Ps = Vs + KT * VP;

    const int tid = threadIdx.x;
    const int ty = tid >> 4;
    const int tx = tid & 15;
    const int b = blockIdx.z, h = blockIdx.y;
    const int q0 = blockIdx.x * QT;
    const float scale = 0.08838834764831845f;

    const float* Qg = Q + ((size_t)(b * S_LEN + q0)) * D_DIM + h * HDIM;
#pragma unroll
    for (int i = 0; i < 8; i++) {
        int idx = tid + i * 256;
        int r = idx >> 5, c = (idx & 31) << 2;
        float4 v4 = *(const float4*)(Qg + (size_t)r * D_DIM + c);
        *(float4*)(Qs + r * QP + c) = v4;
    }

    float m_run[4], l_run[4], acc[4][8];
#pragma unroll
    for (int i = 0; i < 4; i++) {
        m_run[i] = -1e30f; l_run[i] = 0.0f;
#pragma unroll
        for (int j = 0; j < 8; j++) acc[i][j] = 0.0f;
    }

    const int lastTile = q0 >> 6;
    int wstart = (q0 >= WIN) ? ((q0 - (WIN - 1)) >> 6) : 0;
    if (wstart < 1) wstart = 1;

    for (int kt = 0; kt <= lastTile; kt++) {
        if (kt != 0 && kt < wstart) continue;
        const int kb = kt * KT;

        __syncthreads();
        const float* Kg = K + ((size_t)(b * S_LEN + kb)) * D_DIM + h * HDIM;
        const float* Vg = V + ((size_t)(b * S_LEN + kb)) * D_DIM + h * HDIM;
#pragma unroll
        for (int i = 0; i < 8; i++) {
            int idx = tid + i * 256;
            int r = idx >> 5, c = (idx & 31) << 2;
            float4 k4 = *(const float4*)(Kg + (size_t)r * D_DIM + c);
            Ks[r * KP + c + 0] = k4.x;
            Ks[r * KP + c + 1] = k4.y;
            Ks[r * KP + c + 2] = k4.z;
            Ks[r * KP + c + 3] = k4.w;
            float4 v4 = *(const float4*)(Vg + (size_t)r * D_DIM + c);
            *(float4*)(Vs + r * VP + c) = v4;
        }
        __syncthreads();

        float s[4][4];
#pragma unroll
        for (int qi = 0; qi < 4; qi++)
#pragma unroll
            for (int kj = 0; kj < 4; kj++) s[qi][kj] = 0.0f;

        for (int dd = 0; dd < HDIM; dd++) {
            float a[4], bb[4];
#pragma unroll
            for (int qi = 0; qi < 4; qi++) a[qi] = Qs[(ty * 4 + qi) * QP + dd];
#pragma unroll
            for (int kj = 0; kj < 4; kj++) bb[kj] = Ks[(kj * 16 + tx) * KP + dd];
#pragma unroll
            for (int qi = 0; qi < 4; qi++)
#pragma unroll
                for (int kj = 0; kj < 4; kj++)
                    s[qi][kj] = fmaf(a[qi], bb[kj], s[qi][kj]);
        }

#pragma unroll
        for (int qi = 0; qi < 4; qi++) {
            const int qg = q0 + ty * 4 + qi;
#pragma unroll
            for (int kj = 0; kj < 4; kj++) {
                const int kg = kb + kj * 16 + tx;
                const bool valid = (kg <= qg) && ((qg - kg < WIN) || (kg < SINK));
                s[qi][kj] = valid ? s[qi][kj] * scale : -1e30f;
            }
        }

#pragma unroll
        for (int qi = 0; qi < 4; qi++) {
            float tm = fmaxf(fmaxf(s[qi][0], s[qi][1]), fmaxf(s[qi][2], s[qi][3]));
#pragma unroll
            for (int o = 1; o < 16; o <<= 1)
                tm = fmaxf(tm, __shfl_xor_sync(0xffffffffu, tm, o));
            const float m_new = fmaxf(m_run[qi], tm);
            const float p0 = __expf(s[qi][0] - m_new);
            const float p1 = __expf(s[qi][1] - m_new);
            const float p2 = __expf(s[qi][2] - m_new);
            const float p3 = __expf(s[qi][3] - m_new);
            float rs = p0 + p1 + p2 + p3;
#pragma unroll
            for (int o = 1; o < 16; o <<= 1)
                rs += __shfl_xor_sync(0xffffffffu, rs, o);
            const float alpha = __expf(m_run[qi] - m_new);
            l_run[qi] = l_run[qi] * alpha + rs;
            m_run[qi] = m_new;
#pragma unroll
            for (int j = 0; j < 8; j++) acc[qi][j] *= alpha;
            Ps[(ty * 4 + qi) * PP + 0 * 16 + tx] = p0;
            Ps[(ty * 4 + qi) * PP + 1 * 16 + tx] = p1;
            Ps[(ty * 4 + qi) * PP + 2 * 16 + tx] = p2;
            Ps[(ty * 4 + qi) * PP + 3 * 16 + tx] = p3;
        }
        __syncthreads();

        for (int kk = 0; kk < KT; kk++) {
            float vv[8];
#pragma unroll
            for (int j = 0; j < 8; j++) vv[j] = Vs[kk * VP + j * 16 + tx];
#pragma unroll
            for (int qi = 0; qi < 4; qi++) {
                const float p = Ps[(ty * 4 + qi) * PP + kk];
#pragma unroll
                for (int j = 0; j < 8; j++)
                    acc[qi][j] = fmaf(p, vv[j], acc[qi][j]);
            }
        }
    }

    const size_t obase = ((size_t)(b * S_LEN + q0 + ty * 4)) * D_DIM + h * HDIM;
#pragma unroll
    for (int qi = 0; qi < 4; qi++) {
        const float inv = 1.0f / l_run[qi];
#pragma unroll
        for (int j = 0; j < 8; j++) {
            float v = acc[qi][j] * inv;
            __nv_bfloat16 hh = __float2bfloat16(v);
            size_t o = obase + (size_t)qi * D_DIM + j * 16 + tx;
            Oh[o] = hh;
            Ol[o] = __float2bfloat16(v - __bfloat162float(hh));
        }
    }
}

// ---------------- launch ------------------------------------------------------
extern "C" void kernel_launch(void* const* d_in, const int* in_sizes, int n_in,
                              void* d_out, int out_size)
{
    const float* x   = (const float*)d_in[0];
    const float* Wq  = (const float*)d_in[1];
    const float* Wkv = (const float*)d_in[2];
    const float* Wk  = (const float*)d_in[3];
    const float* Wv  = (const float*)d_in[4];
    const float* Wo  = (const float*)d_in[5];
    float* out = (float*)d_out;

    float *Q, *K, *V;
    cudaGetSymbolAddress((void**)&Q, g_Q);
    cudaGetSymbolAddress((void**)&K, g_K);
    cudaGetSymbolAddress((void**)&V, g_V);

    __nv_bfloat16 *Xh, *Xl, *KVh, *KVl, *AOh, *AOl;
    __nv_bfloat16 *WqTh, *WqTl, *WkvTh, *WkvTl, *WkTh, *WkTl, *WvTh, *WvTl, *WoTh, *WoTl;
    cudaGetSymbolAddress((void**)&Xh, g_Xh);   cudaGetSymbolAddress((void**)&Xl, g_Xl);
    cudaGetSymbolAddress((void**)&KVh, g_KVh); cudaGetSymbolAddress((void**)&KVl, g_KVl);
    cudaGetSymbolAddress((void**)&AOh, g_AOh); cudaGetSymbolAddress((void**)&AOl, g_AOl);
    cudaGetSymbolAddress((void**)&WqTh, g_WqTh);   cudaGetSymbolAddress((void**)&WqTl, g_WqTl);
    cudaGetSymbolAddress((void**)&WkvTh, g_WkvTh); cudaGetSymbolAddress((void**)&WkvTl, g_WkvTl);
    cudaGetSymbolAddress((void**)&WkTh, g_WkTh);   cudaGetSymbolAddress((void**)&WkTl, g_WkTl);
    cudaGetSymbolAddress((void**)&WvTh, g_WvTh);   cudaGetSymbolAddress((void**)&WvTl, g_WvTl);
    cudaGetSymbolAddress((void**)&WoTh, g_WoTh);   cudaGetSymbolAddress((void**)&WoTl, g_WoTl);

    cudaFuncSetAttribute(mm_kernel, cudaFuncAttributeMaxDynamicSharedMemorySize, MM_SMEM_BYTES);
    cudaFuncSetAttribute(attn_kernel, cudaFuncAttributeMaxDynamicSharedMemorySize, ATTN_SMEM_BYTES);

    const dim3 tb(32, 8);
    // --- conversions ---
    {
        int n4 = MROWS * D_DIM / 4;
        split_kernel<<<(n4 + 255) / 256, 256>>>((const float4*)x, (__nv_bfloat162*)Xh, (__nv_bfloat162*)Xl, n4);
    }
    tsplit_kernel<<<dim3(D_DIM / 32, D_DIM / 32), tb>>>(Wq,  WqTh,  WqTl,  D_DIM, D_DIM);
    tsplit_kernel<<<dim3(L_DIM / 32, D_DIM / 32), tb>>>(Wkv, WkvTh, WkvTl, D_DIM, L_DIM);
    tsplit_kernel<<<dim3(D_DIM / 32, L_DIM / 32), tb>>>(Wk,  WkTh,  WkTl,  L_DIM, D_DIM);
    tsplit_kernel<<<dim3(D_DIM / 32, L_DIM / 32), tb>>>(Wv,  WvTh,  WvTl,  L_DIM, D_DIM);
    tsplit_kernel<<<dim3(D_DIM / 32, D_DIM / 32), tb>>>(Wo,  WoTh,  WoTl,  D_DIM, D_DIM);

    // --- Q = X @ Wq (fp32 out) ---
    mm_kernel<<<dim3(D_DIM / 128, MROWS / 128), 256, MM_SMEM_BYTES>>>(
        Xh, Xl, WqTh, WqTl, Q, nullptr, nullptr, D_DIM, D_DIM, 0);
    // --- KV = X @ Wkv (bf16-split out) ---
    mm_kernel<<<dim3(L_DIM / 128, MROWS / 128), 256, MM_SMEM_BYTES>>>(
        Xh, Xl, WkvTh, WkvTl, nullptr, KVh, KVl, L_DIM, D_DIM, 1);
    // --- K = KV @ Wk, V = KV @ Wv (fp32 out) ---
    mm_kernel<<<dim3(D_DIM / 128, MROWS / 128), 256, MM_SMEM_BYTES>>>(
        KVh, KVl, WkTh, WkTl, K, nullptr, nullptr, D_DIM, L_DIM, 0);
    mm_kernel<<<dim3(D_DIM / 128, MROWS / 128), 256, MM_SMEM_BYTES>>>(
        KVh, KVl, WvTh, WvTl, V, nullptr, nullptr, D_DIM, L_DIM, 0);

    // --- attention (writes bf16-split AO) ---
    attn_kernel<<<dim3(S_LEN / QT, NHEADS, B_SZ), 256, ATTN_SMEM_BYTES>>>(Q, K, V, AOh, AOl);

    // --- out = AO @ Wo ---
    mm_kernel<<<dim3(D_DIM / 128, MROWS / 128), 256, MM_SMEM_BYTES>>>(
        AOh, AOl, WoTh, WoTl, out, nullptr, nullptr, D_DIM, D_DIM, 0);
}

// round 4
// speedup vs baseline: 3.3953x; 1.1718x over previous
#include <cuda_runtime.h>
#include <cuda_bf16.h>
#include <cstdint>

// ---------------- problem constants ----------------
#define B_SZ   2
#define S_LEN  2048
#define D_DIM  2048
#define L_DIM  512
#define NHEADS 16
#define HDIM   128
#define WIN    128
#define SINK   16
#define MROWS  (B_SZ * S_LEN)   // 4096

// ---------------- PTX helpers (base sm_103 ISA only) ----------------
__device__ __forceinline__ uint32_t smem_to_u32(const void* p) {
    uint32_t a;
    asm("{ .reg .u64 t; cvta.to.shared.u64 t, %1; cvt.u32.u64 %0, t; }" : "=r"(a) : "l"(p));
    return a;
}

#define CP_ASYNC16(saddr, gaddr) \
    asm volatile("cp.async.cg.shared.global [%0], [%1], 16;" :: "r"(saddr), "l"(gaddr) : "memory")
#define CP_COMMIT()  asm volatile("cp.async.commit_group;" ::: "memory")
#define CP_WAIT2()   asm volatile("cp.async.wait_group 2;" ::: "memory")
#define CP_WAIT1()   asm volatile("cp.async.wait_group 1;" ::: "memory")
#define CP_WAIT0()   asm volatile("cp.async.wait_group 0;" ::: "memory")

#define LDSM4(r, addr) \
    asm volatile("ldmatrix.sync.aligned.m8n8.x4.shared.b16 {%0,%1,%2,%3}, [%4];" \
        : "=r"((r)[0]), "=r"((r)[1]), "=r"((r)[2]), "=r"((r)[3]) : "r"(addr))
#define LDSM4T(r, addr) \
    asm volatile("ldmatrix.sync.aligned.m8n8.x4.trans.shared.b16 {%0,%1,%2,%3}, [%4];" \
        : "=r"((r)[0]), "=r"((r)[1]), "=r"((r)[2]), "=r"((r)[3]) : "r"(addr))

#define MMA16816(d, a, b0, b1) \
    asm volatile("mma.sync.aligned.m16n8k16.row.col.f32.bf16.bf16.f32 " \
        "{%0,%1,%2,%3},{%4,%5,%6,%7},{%8,%9},{%0,%1,%2,%3};" \
        : "+f"((d)[0]), "+f"((d)[1]), "+f"((d)[2]), "+f"((d)[3]) \
        : "r"((a)[0]), "r"((a)[1]), "r"((a)[2]), "r"((a)[3]), "r"(b0), "r"(b1))

__device__ __forceinline__ void split2(float x, float y, uint32_t& hi, uint32_t& lo) {
    __nv_bfloat162 h = __floats2bfloat162_rn(x, y);
    hi = *(uint32_t*)&h;
    __nv_bfloat162 l = __floats2bfloat162_rn(x - __bfloat162float(h.x), y - __bfloat162float(h.y));
    lo = *(uint32_t*)&l;
}

// ---------------- scratch (device globals) ----------------
__device__ __align__(256) __nv_bfloat16 g_Xh  [MROWS * D_DIM];
__device__ __align__(256) __nv_bfloat16 g_Xl  [MROWS * D_DIM];
__device__ __align__(256) __nv_bfloat16 g_KVh [MROWS * L_DIM];
__device__ __align__(256) __nv_bfloat16 g_KVl [MROWS * L_DIM];
__device__ __align__(256) __nv_bfloat16 g_Qh  [MROWS * D_DIM];
__device__ __align__(256) __nv_bfloat16 g_Ql  [MROWS * D_DIM];
__device__ __align__(256) __nv_bfloat16 g_Kh  [MROWS * D_DIM];
__device__ __align__(256) __nv_bfloat16 g_Kl  [MROWS * D_DIM];
__device__ __align__(256) __nv_bfloat16 g_Vh  [MROWS * D_DIM];
__device__ __align__(256) __nv_bfloat16 g_Vl  [MROWS * D_DIM];
__device__ __align__(256) __nv_bfloat16 g_AOh [MROWS * D_DIM];
__device__ __align__(256) __nv_bfloat16 g_AOl [MROWS * D_DIM];
// transposed weights [N, K] (hi/lo bf16 splits)
__device__ __align__(256) __nv_bfloat16 g_WqTh [D_DIM * D_DIM];
__device__ __align__(256) __nv_bfloat16 g_WqTl [D_DIM * D_DIM];
__device__ __align__(256) __nv_bfloat16 g_WkvTh[L_DIM * D_DIM];
__device__ __align__(256) __nv_bfloat16 g_WkvTl[L_DIM * D_DIM];
__device__ __align__(256) __nv_bfloat16 g_WkTh [D_DIM * L_DIM];
__device__ __align__(256) __nv_bfloat16 g_WkTl [D_DIM * L_DIM];
__device__ __align__(256) __nv_bfloat16 g_WvTh [D_DIM * L_DIM];
__device__ __align__(256) __nv_bfloat16 g_WvTl [D_DIM * L_DIM];
__device__ __align__(256) __nv_bfloat16 g_WoTh [D_DIM * D_DIM];
__device__ __align__(256) __nv_bfloat16 g_WoTl [D_DIM * D_DIM];

// ---------------- split conversions ----------------
__global__ void split_kernel(const float4* __restrict__ in,
                             __nv_bfloat162* __restrict__ hi,
                             __nv_bfloat162* __restrict__ lo, int n4)
{
    int i = blockIdx.x * blockDim.x + threadIdx.x;
    if (i >= n4) return;
    float4 v = in[i];
    uint32_t h0, l0, h1, l1;
    split2(v.x, v.y, h0, l0);
    split2(v.z, v.w, h1, l1);
    hi[2 * i]     = *(__nv_bfloat162*)&h0;
    hi[2 * i + 1] = *(__nv_bfloat162*)&h1;
    lo[2 * i]     = *(__nv_bfloat162*)&l0;
    lo[2 * i + 1] = *(__nv_bfloat162*)&l1;
}

// in [K, N] fp32 -> out [N, K] bf16 (hi/lo)
__global__ void tsplit_kernel(const float* __restrict__ in,
                              __nv_bfloat16* __restrict__ hi,
                              __nv_bfloat16* __restrict__ lo,
                              int K, int N)
{
    __shared__ float tile[32][33];
    int kb = blockIdx.y * 32, nb = blockIdx.x * 32;
    int tx = threadIdx.x, ty = threadIdx.y;
#pragma unroll
    for (int j = 0; j < 32; j += 8)
        tile[ty + j][tx] = in[(size_t)(kb + ty + j) * N + nb + tx];
    __syncthreads();
#pragma unroll
    for (int j = 0; j < 32; j += 8) {
        float v = tile[tx][ty + j];
        __nv_bfloat16 h = __float2bfloat16(v);
        __nv_bfloat16 l = __float2bfloat16(v - __bfloat162float(h));
        size_t o = (size_t)(nb + ty + j) * K + kb + tx;
        hi[o] = h; lo[o] = l;
    }
}

// ---------------- bf16-split HMMA GEMM ----------------------------------------
// C[M,N] = A[M,K] @ B^T where B stored [N,K]. C = Ah*Bh + Ah*Bl + Al*Bh (fp32 acc).
// 128x128 CTA tile, BK=64, 8 warps, 3-stage cp.async pipeline.
#define MM_STAGE_BYTES 65536   // 4 tiles * 128 rows * 128B
#define MM_SMEM_BYTES  (3 * MM_STAGE_BYTES)

__device__ __forceinline__ void mm_load_chunk(
    uint32_t sb, int ck, int tid,
    const __nv_bfloat16* __restrict__ Ah, const __nv_bfloat16* __restrict__ Al,
    const __nv_bfloat16* __restrict__ Bh, const __nv_bfloat16* __restrict__ Bl,
    int m0, int n0, int K)
{
    const int k0 = ck * 64;
#pragma unroll
    for (int it = 0; it < 4; it++) {
        int idx = tid + it * 256;      // 0..1023
        int r   = idx >> 3;            // 0..127
        int cb  = (idx & 7) << 4;      // byte col
        uint32_t off = (uint32_t)(r * 128 + cb);
        uint32_t sw  = off ^ ((off >> 3) & 0x70);
        const char* pa  = (const char*)(Ah + (size_t)(m0 + r) * K + k0) + cb;
        const char* pal = (const char*)(Al + (size_t)(m0 + r) * K + k0) + cb;
        const char* pb  = (const char*)(Bh + (size_t)(n0 + r) * K + k0) + cb;
        const char* pbl = (const char*)(Bl + (size_t)(n0 + r) * K + k0) + cb;
        CP_ASYNC16(sb + sw,          pa);
        CP_ASYNC16(sb + 16384u + sw, pal);
        CP_ASYNC16(sb + 32768u + sw, pb);
        CP_ASYNC16(sb + 49152u + sw, pbl);
    }
}

__global__ __launch_bounds__(256, 1)
void mm_kernel(const __nv_bfloat16* __restrict__ Ah,
               const __nv_bfloat16* __restrict__ Al,
               const __nv_bfloat16* __restrict__ Bh,
               const __nv_bfloat16* __restrict__ Bl,
               float* __restrict__ C,
               __nv_bfloat16* __restrict__ Oh,
               __nv_bfloat16* __restrict__ Ol,
               int N, int K, int split_out)
{
    extern __shared__ __align__(1024) char dsm[];
    const uint32_t smem = smem_to_u32(dsm);

    const int tid  = threadIdx.x;
    const int wid  = tid >> 5;
    const int lane = tid & 31;
    const int warp_m = wid & 1;
    const int warp_n = wid >> 1;
    const int m0 = blockIdx.y * 128, n0 = blockIdx.x * 128;

    float d[4][4][4];
#pragma unroll
    for (int mt = 0; mt < 4; mt++)
#pragma unroll
        for (int nt = 0; nt < 4; nt++)
#pragma unroll
            for (int j = 0; j < 4; j++) d[mt][nt][j] = 0.0f;

    const int nch = K / 64;
    mm_load_chunk(smem,                  0, tid, Ah, Al, Bh, Bl, m0, n0, K);
    CP_COMMIT();
    mm_load_chunk(smem + MM_STAGE_BYTES, 1, tid, Ah, Al, Bh, Bl, m0, n0, K);
    CP_COMMIT();

    const int a_row  = warp_m * 64 + (lane & 15);
    const int a_kofs = (lane >> 4) << 4;
    const int b_row  = warp_n * 32 + ((lane >> 4) << 3) + (lane & 7);
    const int b_kofs = ((lane >> 3) & 1) << 4;

    for (int i = 0; i < nch; i++) {
        if (i + 2 < nch) {
            mm_load_chunk(smem + (uint32_t)((i + 2) % 3) * MM_STAGE_BYTES, i + 2, tid,
                          Ah, Al, Bh, Bl, m0, n0, K);
            CP_COMMIT();
            CP_WAIT2();
        } else if (i + 1 < nch) {
            CP_WAIT1();
        } else {
            CP_WAIT0();
        }
        __syncthreads();

        const uint32_t sb = smem + (uint32_t)(i % 3) * MM_STAGE_BYTES;
#pragma unroll
        for (int ks = 0; ks < 4; ks++) {
            const int kb = ks * 32;
            uint32_t ah[4][4], al[4][4], bh[2][4], bl[2][4];
#pragma unroll
            for (int mt = 0; mt < 4; mt++) {
                uint32_t off = (uint32_t)((a_row + mt * 16) * 128 + kb + a_kofs);
                uint32_t sw  = off ^ ((off >> 3) & 0x70);
                LDSM4(ah[mt], sb + sw);
                LDSM4(al[mt], sb + 16384u + sw);
            }
#pragma unroll
            for (int np = 0; np < 2; np++) {
                uint32_t off = (uint32_t)((b_row + np * 16) * 128 + kb + b_kofs);
                uint32_t sw  = off ^ ((off >> 3) & 0x70);
                LDSM4(bh[np], sb + 32768u + sw);
                LDSM4(bl[np], sb + 49152u + sw);
            }
#pragma unroll
            for (int mt = 0; mt < 4; mt++) {
#pragma unroll
                for (int nt = 0; nt < 4; nt++) {
                    const int np = nt >> 1, h = (nt & 1) << 1;
                    MMA16816(d[mt][nt], ah[mt], bh[np][h], bh[np][h + 1]);
                    MMA16816(d[mt][nt], ah[mt], bl[np][h], bl[np][h + 1]);
                    MMA16816(d[mt][nt], al[mt], bh[np][h], bh[np][h + 1]);
                }
            }
        }
        __syncthreads();
    }

    const int gid = lane >> 2, tig = lane & 3;
    const int mbase = m0 + warp_m * 64 + gid;
    const int nbase = n0 + warp_n * 32 + tig * 2;
    if (!split_out) {
#pragma unroll
        for (int mt = 0; mt < 4; mt++)
#pragma unroll
            for (int nt = 0; nt < 4; nt++) {
                const int m = mbase + mt * 16;
                const int n = nbase + nt * 8;
                *(float2*)(C + (size_t)m * N + n)       = make_float2(d[mt][nt][0], d[mt][nt][1]);
                *(float2*)(C + (size_t)(m + 8) * N + n) = make_float2(d[mt][nt][2], d[mt][nt][3]);
            }
    } else {
#pragma unroll
        for (int mt = 0; mt < 4; mt++)
#pragma unroll
            for (int nt = 0; nt < 4; nt++) {
#pragma unroll
                for (int half = 0; half < 2; half++) {
                    const int m = mbase + mt * 16 + half * 8;
                    const int n = nbase + nt * 8;
                    uint32_t hh, ll;
                    split2(d[mt][nt][half * 2], d[mt][nt][half * 2 + 1], hh, ll);
                    *(uint32_t*)(Oh + (size_t)m * N + n) = hh;
                    *(uint32_t*)(Ol + (size_t)m * N + n) = ll;
                }
            }
    }
}

// ---------------- HMMA flash attention (sliding window + sink) -----------------
// QT=128 queries/block, KT=64 keys/tile, 8 warps (each 16 q rows).
// bf16 hi/lo split inputs; 3-pass mma for QK^T and PV; fp32 accum.
#define AQT 128
#define AKT 64
#define A_STAGE_OFF   65536u           // Qh 32KB + Ql 32KB before stages
#define A_STAGE_BYTES 65536u           // Kh,Kl,Vh,Vl (16KB each)
#define A_SMEM_BYTES  (65536 + 2 * 65536)

__global__ __launch_bounds__(256, 1) void attn_kernel(
    const __nv_bfloat16* __restrict__ Qh_g, const __nv_bfloat16* __restrict__ Ql_g,
    const __nv_bfloat16* __restrict__ Kh_g, const __nv_bfloat16* __restrict__ Kl_g,
    const __nv_bfloat16* __restrict__ Vh_g, const __nv_bfloat16* __restrict__ Vl_g,
    __nv_bfloat16* __restrict__ Oh_g, __nv_bfloat16* __restrict__ Ol_g)
{
    extern __shared__ __align__(1024) char dsm[];
    const uint32_t smem = smem_to_u32(dsm);
    const int tid = threadIdx.x, wid = tid >> 5, lane = tid & 31;
    const int b = blockIdx.z, h = blockIdx.y;
    const int q0 = blockIdx.x * AQT;
    const int gid = lane >> 2, tig = lane & 3;
    const int wq = wid * 16;
    const float scale = 0.08838834764831845f;

    // ---- async-load Q (hi/lo), panel layout lrow = (d>>6)*128 + row ----
    {
        const size_t qg = ((size_t)(b * S_LEN + q0)) * D_DIM + h * HDIM;
#pragma unroll
        for (int it = 0; it < 8; it++) {
            int ch = tid + it * 256;          // 0..2047
            int row = ch >> 4, dblk = ch & 15;
            uint32_t lrow = (uint32_t)((dblk >> 3) * 128 + row);
            uint32_t off = lrow * 128 + (dblk & 7) * 16;
            uint32_t sw = off ^ ((off >> 3) & 0x70);
            size_t g = qg + (size_t)row * D_DIM + dblk * 8;
            CP_ASYNC16(smem + sw,           (const char*)(Qh_g + g));
            CP_ASYNC16(smem + 32768u + sw,  (const char*)(Ql_g + g));
        }
        CP_COMMIT();
    }

    // ---- tile schedule: tile 0 (sink), then window tiles ----
    const int ws = q0 - WIN + 1;
    const int tstart = (ws >= 64) ? (ws >> 6) : 1;
    const int tend = (q0 + AQT - 1) >> 6;
    const int cnt = 2 + (tend - tstart);

#define TILE_OF(j) ((j) == 0 ? 0 : (tstart + (j) - 1))
#define LOAD_KV(j) do { \
        int kb_ = TILE_OF(j) * AKT; \
        uint32_t sb_ = smem + A_STAGE_OFF + (uint32_t)((j) & 1) * A_STAGE_BYTES; \
        size_t gb_ = ((size_t)(b * S_LEN + kb_)) * D_DIM + h * HDIM; \
        _Pragma("unroll") \
        for (int it_ = 0; it_ < 4; it_++) { \
            int ch_ = tid + it_ * 256; \
            int row_ = ch_ >> 4, dblk_ = ch_ & 15; \
            uint32_t lrow_ = (uint32_t)((dblk_ >> 3) * 64 + row_); \
            uint32_t off_ = lrow_ * 128 + (dblk_ & 7) * 16; \
            uint32_t sw_ = off_ ^ ((off_ >> 3) & 0x70); \
            size_t g_ = gb_ + (size_t)row_ * D_DIM + dblk_ * 8; \
            CP_ASYNC16(sb_ + sw_,           (const char*)(Kh_g + g_)); \
            CP_ASYNC16(sb_ + 16384u + sw_,  (const char*)(Kl_g + g_)); \
            CP_ASYNC16(sb_ + 32768u + sw_,  (const char*)(Vh_g + g_)); \
            CP_ASYNC16(sb_ + 49152u + sw_,  (const char*)(Vl_g + g_)); \
        } \
        CP_COMMIT(); \
    } while (0)

    LOAD_KV(0);

    float o[16][4];
#pragma unroll
    for (int dt = 0; dt < 16; dt++)
#pragma unroll
        for (int j = 0; j < 4; j++) o[dt][j] = 0.0f;
    float m0r = -1e30f, m1r = -1e30f, l0r = 0.0f, l1r = 0.0f;

    for (int j = 0; j < cnt; j++) {
        if (j + 1 < cnt) { LOAD_KV(j + 1); CP_WAIT1(); }
        else             { CP_WAIT0(); }
        __syncthreads();

        const uint32_t sb = smem + A_STAGE_OFF + (uint32_t)(j & 1) * A_STAGE_BYTES;
        const int kb = TILE_OF(j) * AKT;

        // ---- S = Q K^T (3 passes) ----
        float s[8][4];
#pragma unroll
        for (int nt = 0; nt < 8; nt++)
#pragma unroll
            for (int jj = 0; jj < 4; jj++) s[nt][jj] = 0.0f;

#pragma unroll
        for (int ks = 0; ks < 8; ks++) {
            uint32_t ah[4], al[4];
            {
                int dd = ks * 16 + ((lane >> 4) << 3);
                int row = wq + (lane & 15);
                uint32_t lrow = (uint32_t)((dd >> 6) * 128 + row);
                uint32_t off = lrow * 128 + (dd & 63) * 2;
                uint32_t sw = off ^ ((off >> 3) & 0x70);
                LDSM4(ah, smem + sw);
                LDSM4(al, smem + 32768u + sw);
            }
#pragma unroll
            for (int np = 0; np < 4; np++) {
                uint32_t bh[4], bl[4];
                int key = np * 16 + ((lane >> 4) << 3) + (lane & 7);
                int dd = ks * 16 + ((lane >> 3) & 1) * 8;
                uint32_t lrow = (uint32_t)((dd >> 6) * 64 + key);
                uint32_t off = lrow * 128 + (dd & 63) * 2;
                uint32_t sw = off ^ ((off >> 3) & 0x70);
                LDSM4(bh, sb + sw);
                LDSM4(bl, sb + 16384u + sw);
#pragma unroll
                for (int t = 0; t < 2; t++) {
                    MMA16816(s[np * 2 + t], ah, bh[2 * t], bh[2 * t + 1]);
                    MMA16816(s[np * 2 + t], ah, bl[2 * t], bl[2 * t + 1]);
                    MMA16816(s[np * 2 + t], al, bh[2 * t], bh[2 * t + 1]);
                }
            }
        }

        // ---- mask + scale ----
#pragma unroll
        for (int nt = 0; nt < 8; nt++) {
            const int kc = kb + nt * 8 + tig * 2;
#pragma unroll
            for (int jj = 0; jj < 4; jj++) {
                const int q = q0 + wq + gid + ((jj >> 1) << 3);
                const int k = kc + (jj & 1);
                const bool valid = (k <= q) && ((q - k < WIN) || (k < SINK));
                s[nt][jj] = valid ? s[nt][jj] * scale : -1e30f;
            }
        }

        // ---- online softmax (rows gid, gid+8; reduce across tig lanes) ----
        float tm0 = -1e30f, tm1 = -1e30f;
#pragma unroll
        for (int nt = 0; nt < 8; nt++) {
            tm0 = fmaxf(tm0, fmaxf(s[nt][0], s[nt][1]));
            tm1 = fmaxf(tm1, fmaxf(s[nt][2], s[nt][3]));
        }
        tm0 = fmaxf(tm0, __shfl_xor_sync(0xffffffffu, tm0, 1));
        tm0 = fmaxf(tm0, __shfl_xor_sync(0xffffffffu, tm0, 2));
        tm1 = fmaxf(tm1, __shfl_xor_sync(0xffffffffu, tm1, 1));
        tm1 = fmaxf(tm1, __shfl_xor_sync(0xffffffffu, tm1, 2));
        const float m0n = fmaxf(m0r, tm0), m1n = fmaxf(m1r, tm1);
        const float al0 = __expf(m0r - m0n), al1 = __expf(m1r - m1n);
        m0r = m0n; m1r = m1n;

        float rs0 = 0.0f, rs1 = 0.0f;
#pragma unroll
        for (int nt = 0; nt < 8; nt++) {
            float p0 = __expf(s[nt][0] - m0n);
            float p1 = __expf(s[nt][1] - m0n);
            float p2 = __expf(s[nt][2] - m1n);
            float p3 = __expf(s[nt][3] - m1n);
            s[nt][0] = p0; s[nt][1] = p1; s[nt][2] = p2; s[nt][3] = p3;
            rs0 += p0 + p1; rs1 += p2 + p3;
        }
        rs0 += __shfl_xor_sync(0xffffffffu, rs0, 1);
        rs0 += __shfl_xor_sync(0xffffffffu, rs0, 2);
        rs1 += __shfl_xor_sync(0xffffffffu, rs1, 1);
        rs1 += __shfl_xor_sync(0xffffffffu, rs1, 2);
        l0r = l0r * al0 + rs0;
        l1r = l1r * al1 + rs1;

#pragma unroll
        for (int dt = 0; dt < 16; dt++) {
            o[dt][0] *= al0; o[dt][1] *= al0;
            o[dt][2] *= al1; o[dt][3] *= al1;
        }

        // ---- P -> bf16 split A-fragments ----
        uint32_t ph[4][4], pl[4][4];
#pragma unroll
        for (int ks = 0; ks < 4; ks++) {
            split2(s[2 * ks][0],     s[2 * ks][1],     ph[ks][0], pl[ks][0]);
            split2(s[2 * ks][2],     s[2 * ks][3],     ph[ks][1], pl[ks][1]);
            split2(s[2 * ks + 1][0], s[2 * ks + 1][1], ph[ks][2], pl[ks][2]);
            split2(s[2 * ks + 1][2], s[2 * ks + 1][3], ph[ks][3], pl[ks][3]);
        }

        // ---- O += P @ V (3 passes, V via ldmatrix.trans) ----
#pragma unroll
        for (int np = 0; np < 8; np++) {
#pragma unroll
            for (int ks = 0; ks < 4; ks++) {
                uint32_t vh[4], vl[4];
                int key = ks * 16 + (lane & 7) + ((lane >> 3) & 1) * 8;
                int dd = np * 16 + ((lane >> 4) << 3);
                uint32_t lrow = (uint32_t)((dd >> 6) * 64 + key);
                uint32_t off = lrow * 128 + (dd & 63) * 2;
                uint32_t sw = off ^ ((off >> 3) & 0x70);
                LDSM4T(vh, sb + 32768u + sw);
                LDSM4T(vl, sb + 49152u + sw);
#pragma unroll
                for (int t = 0; t < 2; t++) {
                    MMA16816(o[np * 2 + t], ph[ks], vh[2 * t], vh[2 * t + 1]);
                    MMA16816(o[np * 2 + t], ph[ks], vl[2 * t], vl[2 * t + 1]);
                    MMA16816(o[np * 2 + t], pl[ks], vh[2 * t], vh[2 * t + 1]);
                }
            }
        }
        __syncthreads();
    }

    // ---- normalize + write bf16-split O ----
    const float inv0 = 1.0f / l0r, inv1 = 1.0f / l1r;
    const size_t ob = ((size_t)(b * S_LEN + q0 + wq)) * D_DIM + h * HDIM;
#pragma unroll
    for (int dt = 0; dt < 16; dt++) {
        const int dd = dt * 8 + tig * 2;
        uint32_t hh, ll;
        split2(o[dt][0] * inv0, o[dt][1] * inv0, hh, ll);
        *(uint32_t*)(Oh_g + ob + (size_t)gid * D_DIM + dd) = hh;
        *(uint32_t*)(Ol_g + ob + (size_t)gid * D_DIM + dd) = ll;
        split2(o[dt][2] * inv1, o[dt][3] * inv1, hh, ll);
        *(uint32_t*)(Oh_g + ob + (size_t)(gid + 8) * D_DIM + dd) = hh;
        *(uint32_t*)(Ol_g + ob + (size_t)(gid + 8) * D_DIM + dd) = ll;
    }
}

// ---------------- launch ------------------------------------------------------
extern "C" void kernel_launch(void* const* d_in, const int* in_sizes, int n_in,
                              void* d_out, int out_size)
{
    const float* x   = (const float*)d_in[0];
    const float* Wq  = (const float*)d_in[1];
    const float* Wkv = (const float*)d_in[2];
    const float* Wk  = (const float*)d_in[3];
    const float* Wv  = (const float*)d_in[4];
    const float* Wo  = (const float*)d_in[5];
    float* out = (float*)d_out;

    __nv_bfloat16 *Xh, *Xl, *KVh, *KVl, *Qh, *Ql, *Kh, *Kl, *Vh, *Vl, *AOh, *AOl;
    __nv_bfloat16 *WqTh, *WqTl, *WkvTh, *WkvTl, *WkTh, *WkTl, *WvTh, *WvTl, *WoTh, *WoTl;
    cudaGetSymbolAddress((void**)&Xh, g_Xh);   cudaGetSymbolAddress((void**)&Xl, g_Xl);
    cudaGetSymbolAddress((void**)&KVh, g_KVh); cudaGetSymbolAddress((void**)&KVl, g_KVl);
    cudaGetSymbolAddress((void**)&Qh, g_Qh);   cudaGetSymbolAddress((void**)&Ql, g_Ql);
    cudaGetSymbolAddress((void**)&Kh, g_Kh);   cudaGetSymbolAddress((void**)&Kl, g_Kl);
    cudaGetSymbolAddress((void**)&Vh, g_Vh);   cudaGetSymbolAddress((void**)&Vl, g_Vl);
    cudaGetSymbolAddress((void**)&AOh, g_AOh); cudaGetSymbolAddress((void**)&AOl, g_AOl);
    cudaGetSymbolAddress((void**)&WqTh, g_WqTh);   cudaGetSymbolAddress((void**)&WqTl, g_WqTl);
    cudaGetSymbolAddress((void**)&WkvTh, g_WkvTh); cudaGetSymbolAddress((void**)&WkvTl, g_WkvTl);
    cudaGetSymbolAddress((void**)&WkTh, g_WkTh);   cudaGetSymbolAddress((void**)&WkTl, g_WkTl);
    cudaGetSymbolAddress((void**)&WvTh, g_WvTh);   cudaGetSymbolAddress((void**)&WvTl, g_WvTl);
    cudaGetSymbolAddress((void**)&WoTh, g_WoTh);   cudaGetSymbolAddress((void**)&WoTl, g_WoTl);

    cudaFuncSetAttribute(mm_kernel,  cudaFuncAttributeMaxDynamicSharedMemorySize, MM_SMEM_BYTES);
    cudaFuncSetAttribute(attn_kernel, cudaFuncAttributeMaxDynamicSharedMemorySize, A_SMEM_BYTES);

    const dim3 tb(32, 8);
    // --- conversions ---
    {
        int n4 = MROWS * D_DIM / 4;
        split_kernel<<<(n4 + 255) / 256, 256>>>((const float4*)x, (__nv_bfloat162*)Xh, (__nv_bfloat162*)Xl, n4);
    }
    tsplit_kernel<<<dim3(D_DIM / 32, D_DIM / 32), tb>>>(Wq,  WqTh,  WqTl,  D_DIM, D_DIM);
    tsplit_kernel<<<dim3(L_DIM / 32, D_DIM / 32), tb>>>(Wkv, WkvTh, WkvTl, D_DIM, L_DIM);
    tsplit_kernel<<<dim3(D_DIM / 32, L_DIM / 32), tb>>>(Wk,  WkTh,  WkTl,  L_DIM, D_DIM);
    tsplit_kernel<<<dim3(D_DIM / 32, L_DIM / 32), tb>>>(Wv,  WvTh,  WvTl,  L_DIM, D_DIM);
    tsplit_kernel<<<dim3(D_DIM / 32, D_DIM / 32), tb>>>(Wo,  WoTh,  WoTl,  D_DIM, D_DIM);

    // --- projections (all bf16-split outputs) ---
    mm_kernel<<<dim3(D_DIM / 128, MROWS / 128), 256, MM_SMEM_BYTES>>>(
        Xh, Xl, WqTh, WqTl, nullptr, Qh, Ql, D_DIM, D_DIM, 1);
    mm_kernel<<<dim3(L_DIM / 128, MROWS / 128), 256, MM_SMEM_BYTES>>>(
        Xh, Xl, WkvTh, WkvTl, nullptr, KVh, KVl, L_DIM, D_DIM, 1);
    mm_kernel<<<dim3(D_DIM / 128, MROWS / 128), 256, MM_SMEM_BYTES>>>(
        KVh, KVl, WkTh, WkTl, nullptr, Kh, Kl, D_DIM, L_DIM, 1);
    mm_kernel<<<dim3(D_DIM / 128, MROWS / 128), 256, MM_SMEM_BYTES>>>(
        KVh, KVl, WvTh, WvTl, nullptr, Vh, Vl, D_DIM, L_DIM, 1);

    // --- attention (HMMA, bf16-split in/out) ---
    attn_kernel<<<dim3(S_LEN / AQT, NHEADS, B_SZ), 256, A_SMEM_BYTES>>>(
        Qh, Ql, Kh, Kl, Vh, Vl, AOh, AOl);

    // --- out = AO @ Wo (fp32 out) ---
    mm_kernel<<<dim3(D_DIM / 128, MROWS / 128), 256, MM_SMEM_BYTES>>>(
        AOh, AOl, WoTh, WoTl, out, nullptr, nullptr, D_DIM, D_DIM, 0);
}

// round 5
// speedup vs baseline: 3.4458x; 1.0149x over previous
#include <cuda_runtime.h>
#include <cuda_bf16.h>
#include <cstdint>

// ---------------- problem constants ----------------
#define B_SZ   2
#define S_LEN  2048
#define D_DIM  2048
#define L_DIM  512
#define NHEADS 16
#define HDIM   128
#define WIN    128
#define SINK   16
#define MROWS  (B_SZ * S_LEN)   // 4096

// ---------------- PTX helpers (base sm_103 ISA only) ----------------
__device__ __forceinline__ uint32_t smem_to_u32(const void* p) {
    uint32_t a;
    asm("{ .reg .u64 t; cvta.to.shared.u64 t, %1; cvt.u32.u64 %0, t; }" : "=r"(a) : "l"(p));
    return a;
}

#define CP_ASYNC16(saddr, gaddr) \
    asm volatile("cp.async.cg.shared.global [%0], [%1], 16;" :: "r"(saddr), "l"(gaddr) : "memory")
#define CP_COMMIT()  asm volatile("cp.async.commit_group;" ::: "memory")
#define CP_WAIT2()   asm volatile("cp.async.wait_group 2;" ::: "memory")
#define CP_WAIT1()   asm volatile("cp.async.wait_group 1;" ::: "memory")
#define CP_WAIT0()   asm volatile("cp.async.wait_group 0;" ::: "memory")

#define LDSM4(r, addr) \
    asm volatile("ldmatrix.sync.aligned.m8n8.x4.shared.b16 {%0,%1,%2,%3}, [%4];" \
        : "=r"((r)[0]), "=r"((r)[1]), "=r"((r)[2]), "=r"((r)[3]) : "r"(addr))
#define LDSM4T(r, addr) \
    asm volatile("ldmatrix.sync.aligned.m8n8.x4.trans.shared.b16 {%0,%1,%2,%3}, [%4];" \
        : "=r"((r)[0]), "=r"((r)[1]), "=r"((r)[2]), "=r"((r)[3]) : "r"(addr))

#define MMA16816(d, a, b0, b1) \
    asm volatile("mma.sync.aligned.m16n8k16.row.col.f32.bf16.bf16.f32 " \
        "{%0,%1,%2,%3},{%4,%5,%6,%7},{%8,%9},{%0,%1,%2,%3};" \
        : "+f"((d)[0]), "+f"((d)[1]), "+f"((d)[2]), "+f"((d)[3]) \
        : "r"((a)[0]), "r"((a)[1]), "r"((a)[2]), "r"((a)[3]), "r"(b0), "r"(b1))

__device__ __forceinline__ void split2(float x, float y, uint32_t& hi, uint32_t& lo) {
    __nv_bfloat162 h = __floats2bfloat162_rn(x, y);
    hi = *(uint32_t*)&h;
    __nv_bfloat162 l = __floats2bfloat162_rn(x - __bfloat162float(h.x), y - __bfloat162float(h.y));
    lo = *(uint32_t*)&l;
}

// ---------------- scratch (device globals) ----------------
__device__ __align__(256) __nv_bfloat16 g_Xh  [MROWS * D_DIM];
__device__ __align__(256) __nv_bfloat16 g_Xl  [MROWS * D_DIM];
__device__ __align__(256) __nv_bfloat16 g_KVh [MROWS * L_DIM];
__device__ __align__(256) __nv_bfloat16 g_KVl [MROWS * L_DIM];
__device__ __align__(256) __nv_bfloat16 g_Qh  [MROWS * D_DIM];
__device__ __align__(256) __nv_bfloat16 g_Ql  [MROWS * D_DIM];
__device__ __align__(256) __nv_bfloat16 g_Kh  [MROWS * D_DIM];
__device__ __align__(256) __nv_bfloat16 g_Kl  [MROWS * D_DIM];
__device__ __align__(256) __nv_bfloat16 g_Vh  [MROWS * D_DIM];
__device__ __align__(256) __nv_bfloat16 g_Vl  [MROWS * D_DIM];
__device__ __align__(256) __nv_bfloat16 g_AOh [MROWS * D_DIM];
__device__ __align__(256) __nv_bfloat16 g_AOl [MROWS * D_DIM];
// merged transposed weights:
// W1 = [WqT ; WkvT]  -> [2560, 2048]
// W2 = [WkT ; WvT]   -> [4096, 512]
__device__ __align__(256) __nv_bfloat16 g_W1h[(D_DIM + L_DIM) * D_DIM];
__device__ __align__(256) __nv_bfloat16 g_W1l[(D_DIM + L_DIM) * D_DIM];
__device__ __align__(256) __nv_bfloat16 g_W2h[(2 * D_DIM) * L_DIM];
__device__ __align__(256) __nv_bfloat16 g_W2l[(2 * D_DIM) * L_DIM];
__device__ __align__(256) __nv_bfloat16 g_WoTh[D_DIM * D_DIM];
__device__ __align__(256) __nv_bfloat16 g_WoTl[D_DIM * D_DIM];

// ---------------- split conversions ----------------
__global__ void split_kernel(const float4* __restrict__ in,
                             __nv_bfloat162* __restrict__ hi,
                             __nv_bfloat162* __restrict__ lo, int n4)
{
    int i = blockIdx.x * blockDim.x + threadIdx.x;
    if (i >= n4) return;
    float4 v = in[i];
    uint32_t h0, l0, h1, l1;
    split2(v.x, v.y, h0, l0);
    split2(v.z, v.w, h1, l1);
    hi[2 * i]     = *(__nv_bfloat162*)&h0;
    hi[2 * i + 1] = *(__nv_bfloat162*)&h1;
    lo[2 * i]     = *(__nv_bfloat162*)&l0;
    lo[2 * i + 1] = *(__nv_bfloat162*)&l1;
}

// in [K, N] fp32 -> out [N, K] bf16 (hi/lo)
__global__ void tsplit_kernel(const float* __restrict__ in,
                              __nv_bfloat16* __restrict__ hi,
                              __nv_bfloat16* __restrict__ lo,
                              int K, int N)
{
    __shared__ float tile[32][33];
    int kb = blockIdx.y * 32, nb = blockIdx.x * 32;
    int tx = threadIdx.x, ty = threadIdx.y;
#pragma unroll
    for (int j = 0; j < 32; j += 8)
        tile[ty + j][tx] = in[(size_t)(kb + ty + j) * N + nb + tx];
    __syncthreads();
#pragma unroll
    for (int j = 0; j < 32; j += 8) {
        float v = tile[tx][ty + j];
        __nv_bfloat16 h = __float2bfloat16(v);
        __nv_bfloat16 l = __float2bfloat16(v - __bfloat162float(h));
        size_t o = (size_t)(nb + ty + j) * K + kb + tx;
        hi[o] = h; lo[o] = l;
    }
}

// ---------------- bf16-split HMMA GEMM (occupancy 2) ---------------------------
// C[M,N] = A[M,K] @ B^T, B stored [N,K]. C = Ah*Bh + Ah*Bl + Al*Bh (fp32 acc).
// 128x128 CTA tile, BK=32, 8 warps, 3-stage cp.async pipeline, SW64 swizzle,
// 96KB smem -> 2 CTAs/SM.
#define MM_STAGE_BYTES 32768u   // Ah,Al,Bh,Bl: 4 x 128 rows x 64B
#define MM_SMEM_BYTES  (3 * 32768)

__device__ __forceinline__ uint32_t sw64(uint32_t off) {
    return off ^ ((off >> 3) & 0x30);
}

__device__ __forceinline__ void mm_load_chunk(
    uint32_t sb, int ck, int tid,
    const __nv_bfloat16* __restrict__ Ah, const __nv_bfloat16* __restrict__ Al,
    const __nv_bfloat16* __restrict__ Bh, const __nv_bfloat16* __restrict__ Bl,
    int m0, int n0, int K)
{
    const int k0 = ck * 32;
#pragma unroll
    for (int it = 0; it < 8; it++) {
        const int arr = it >> 1;                      // 0:Ah 1:Al 2:Bh 3:Bl
        const int u   = ((it & 1) << 8) + tid;        // 0..511
        const int r   = u >> 2;                       // 0..127
        const int cb  = (u & 3) << 4;                 // byte col in 64B row
        const uint32_t sw = sw64((uint32_t)(r * 64 + cb));
        const __nv_bfloat16* base =
            (arr == 0) ? Ah : (arr == 1) ? Al : (arr == 2) ? Bh : Bl;
        const int row0 = (arr < 2) ? m0 : n0;
        const char* g = (const char*)(base + (size_t)(row0 + r) * K + k0) + cb;
        CP_ASYNC16(sb + (uint32_t)arr * 8192u + sw, g);
    }
}

__global__ __launch_bounds__(256, 2)
void mm_kernel(const __nv_bfloat16* __restrict__ Ah,
               const __nv_bfloat16* __restrict__ Al,
               const __nv_bfloat16* __restrict__ Bh,
               const __nv_bfloat16* __restrict__ Bl,
               float* __restrict__ C,
               __nv_bfloat16* __restrict__ Oh_a, __nv_bfloat16* __restrict__ Ol_a,
               int ncols_a,
               __nv_bfloat16* __restrict__ Oh_b, __nv_bfloat16* __restrict__ Ol_b,
               int ncols_b,
               int nsplit, int K, int split_out)
{
    extern __shared__ __align__(1024) char dsm[];
    const uint32_t smem = smem_to_u32(dsm);

    const int tid  = threadIdx.x;
    const int wid  = tid >> 5;
    const int lane = tid & 31;
    const int warp_m = wid & 1;
    const int warp_n = wid >> 1;
    const int m0 = blockIdx.y * 128, n0 = blockIdx.x * 128;

    float d[4][4][4];
#pragma unroll
    for (int mt = 0; mt < 4; mt++)
#pragma unroll
        for (int nt = 0; nt < 4; nt++)
#pragma unroll
            for (int j = 0; j < 4; j++) d[mt][nt][j] = 0.0f;

    const int nch = K / 32;
    mm_load_chunk(smem,          0, tid, Ah, Al, Bh, Bl, m0, n0, K);
    CP_COMMIT();
    mm_load_chunk(smem + 32768u, 1, tid, Ah, Al, Bh, Bl, m0, n0, K);
    CP_COMMIT();

    // ldmatrix lane address components
    const int a_row  = warp_m * 64 + (lane & 15);
    const int a_kofs = (lane >> 4) << 4;                 // 0/16 bytes
    const int b_row  = warp_n * 32 + ((lane >> 4) << 3) + (lane & 7);
    const int b_kofs = ((lane >> 3) & 1) << 4;           // 0/16 bytes

    for (int i = 0; i < nch; i++) {
        if (i + 2 < nch) {
            mm_load_chunk(smem + (uint32_t)((i + 2) % 3) * 32768u, i + 2, tid,
                          Ah, Al, Bh, Bl, m0, n0, K);
            CP_COMMIT();
            CP_WAIT2();
        } else if (i + 1 < nch) {
            CP_WAIT1();
        } else {
            CP_WAIT0();
        }
        __syncthreads();

        const uint32_t sb = smem + (uint32_t)(i % 3) * 32768u;
#pragma unroll
        for (int ks = 0; ks < 2; ks++) {
            const int kb = ks * 32;   // byte offset of 16-elem k-step
            uint32_t bh[2][4], bl[2][4];
#pragma unroll
            for (int np = 0; np < 2; np++) {
                const uint32_t sw = sw64((uint32_t)((b_row + np * 16) * 64 + kb + b_kofs));
                LDSM4(bh[np], sb + 16384u + sw);
                LDSM4(bl[np], sb + 24576u + sw);
            }
#pragma unroll
            for (int mt = 0; mt < 4; mt++) {
                uint32_t ah[4], al[4];
                const uint32_t sw = sw64((uint32_t)((a_row + mt * 16) * 64 + kb + a_kofs));
                LDSM4(ah, sb + sw);
                LDSM4(al, sb + 8192u + sw);
#pragma unroll
                for (int nt = 0; nt < 4; nt++) {
                    const int np = nt >> 1, h = (nt & 1) << 1;
                    MMA16816(d[mt][nt], ah, bh[np][h], bh[np][h + 1]);
                    MMA16816(d[mt][nt], ah, bl[np][h], bl[np][h + 1]);
                    MMA16816(d[mt][nt], al, bh[np][h], bh[np][h + 1]);
                }
            }
        }
        __syncthreads();
    }

    // epilogue
    const int gid = lane >> 2, tig = lane & 3;
    const int mbase = m0 + warp_m * 64 + gid;
    if (!split_out) {
        const int nbase = n0 + warp_n * 32 + tig * 2;
#pragma unroll
        for (int mt = 0; mt < 4; mt++)
#pragma unroll
            for (int nt = 0; nt < 4; nt++) {
                const int m = mbase + mt * 16;
                const int n = nbase + nt * 8;
                *(float2*)(C + (size_t)m * ncols_a + n)       = make_float2(d[mt][nt][0], d[mt][nt][1]);
                *(float2*)(C + (size_t)(m + 8) * ncols_a + n) = make_float2(d[mt][nt][2], d[mt][nt][3]);
            }
    } else {
        const bool second = (n0 >= nsplit);
        __nv_bfloat16* oh = second ? Oh_b : Oh_a;
        __nv_bfloat16* ol = second ? Ol_b : Ol_a;
        const int nc = second ? ncols_b : ncols_a;
        const int nbase = (second ? n0 - nsplit : n0) + warp_n * 32 + tig * 2;
#pragma unroll
        for (int mt = 0; mt < 4; mt++)
#pragma unroll
            for (int nt = 0; nt < 4; nt++) {
#pragma unroll
                for (int half = 0; half < 2; half++) {
                    const int m = mbase + mt * 16 + half * 8;
                    const int n = nbase + nt * 8;
                    uint32_t hh, ll;
                    split2(d[mt][nt][half * 2], d[mt][nt][half * 2 + 1], hh, ll);
                    *(uint32_t*)(oh + (size_t)m * nc + n) = hh;
                    *(uint32_t*)(ol + (size_t)m * nc + n) = ll;
                }
            }
    }
}

// ---------------- HMMA flash attention (sliding window + sink) -----------------
#define AQT 128
#define AKT 64
#define A_STAGE_OFF   65536u
#define A_STAGE_BYTES 65536u
#define A_SMEM_BYTES  (65536 + 2 * 65536)

__global__ __launch_bounds__(256, 1) void attn_kernel(
    const __nv_bfloat16* __restrict__ Qh_g, const __nv_bfloat16* __restrict__ Ql_g,
    const __nv_bfloat16* __restrict__ Kh_g, const __nv_bfloat16* __restrict__ Kl_g,
    const __nv_bfloat16* __restrict__ Vh_g, const __nv_bfloat16* __restrict__ Vl_g,
    __nv_bfloat16* __restrict__ Oh_g, __nv_bfloat16* __restrict__ Ol_g)
{
    extern __shared__ __align__(1024) char dsm[];
    const uint32_t smem = smem_to_u32(dsm);
    const int tid = threadIdx.x, wid = tid >> 5, lane = tid & 31;
    const int b = blockIdx.z, h = blockIdx.y;
    const int q0 = blockIdx.x * AQT;
    const int gid = lane >> 2, tig = lane & 3;
    const int wq = wid * 16;
    const float scale = 0.08838834764831845f;

    // ---- async-load Q (hi/lo), panel layout lrow = (d>>6)*128 + row ----
    {
        const size_t qg = ((size_t)(b * S_LEN + q0)) * D_DIM + h * HDIM;
#pragma unroll
        for (int it = 0; it < 8; it++) {
            int ch = tid + it * 256;
            int row = ch >> 4, dblk = ch & 15;
            uint32_t lrow = (uint32_t)((dblk >> 3) * 128 + row);
            uint32_t off = lrow * 128 + (dblk & 7) * 16;
            uint32_t sw = off ^ ((off >> 3) & 0x70);
            size_t g = qg + (size_t)row * D_DIM + dblk * 8;
            CP_ASYNC16(smem + sw,          (const char*)(Qh_g + g));
            CP_ASYNC16(smem + 32768u + sw, (const char*)(Ql_g + g));
        }
        CP_COMMIT();
    }

    const int ws = q0 - WIN + 1;
    const int tstart = (ws >= 64) ? (ws >> 6) : 1;
    const int tend = (q0 + AQT - 1) >> 6;
    const int cnt = 2 + (tend - tstart);

#define TILE_OF(j) ((j) == 0 ? 0 : (tstart + (j) - 1))
#define LOAD_KV(j) do { \
        int kb_ = TILE_OF(j) * AKT; \
        uint32_t sb_ = smem + A_STAGE_OFF + (uint32_t)((j) & 1) * A_STAGE_BYTES; \
        size_t gb_ = ((size_t)(b * S_LEN + kb_)) * D_DIM + h * HDIM; \
        _Pragma("unroll") \
        for (int it_ = 0; it_ < 4; it_++) { \
            int ch_ = tid + it_ * 256; \
            int row_ = ch_ >> 4, dblk_ = ch_ & 15; \
            uint32_t lrow_ = (uint32_t)((dblk_ >> 3) * 64 + row_); \
            uint32_t off_ = lrow_ * 128 + (dblk_ & 7) * 16; \
            uint32_t sw_ = off_ ^ ((off_ >> 3) & 0x70); \
            size_t g_ = gb_ + (size_t)row_ * D_DIM + dblk_ * 8; \
            CP_ASYNC16(sb_ + sw_,           (const char*)(Kh_g + g_)); \
            CP_ASYNC16(sb_ + 16384u + sw_,  (const char*)(Kl_g + g_)); \
            CP_ASYNC16(sb_ + 32768u + sw_,  (const char*)(Vh_g + g_)); \
            CP_ASYNC16(sb_ + 49152u + sw_,  (const char*)(Vl_g + g_)); \
        } \
        CP_COMMIT(); \
    } while (0)

    LOAD_KV(0);

    float o[16][4];
#pragma unroll
    for (int dt = 0; dt < 16; dt++)
#pragma unroll
        for (int j = 0; j < 4; j++) o[dt][j] = 0.0f;
    float m0r = -1e30f, m1r = -1e30f, l0r = 0.0f, l1r = 0.0f;

    for (int j = 0; j < cnt; j++) {
        if (j + 1 < cnt) { LOAD_KV(j + 1); CP_WAIT1(); }
        else             { CP_WAIT0(); }
        __syncthreads();

        const uint32_t sb = smem + A_STAGE_OFF + (uint32_t)(j & 1) * A_STAGE_BYTES;
        const int kb = TILE_OF(j) * AKT;

        float s[8][4];
#pragma unroll
        for (int nt = 0; nt < 8; nt++)
#pragma unroll
            for (int jj = 0; jj < 4; jj++) s[nt][jj] = 0.0f;

#pragma unroll
        for (int ks = 0; ks < 8; ks++) {
            uint32_t ah[4], al[4];
            {
                int dd = ks * 16 + ((lane >> 4) << 3);
                int row = wq + (lane & 15);
                uint32_t lrow = (uint32_t)((dd >> 6) * 128 + row);
                uint32_t off = lrow * 128 + (dd & 63) * 2;
                uint32_t sw = off ^ ((off >> 3) & 0x70);
                LDSM4(ah, smem + sw);
                LDSM4(al, smem + 32768u + sw);
            }
#pragma unroll
            for (int np = 0; np < 4; np++) {
                uint32_t bh[4], bl[4];
                int key = np * 16 + ((lane >> 4) << 3) + (lane & 7);
                int dd = ks * 16 + ((lane >> 3) & 1) * 8;
                uint32_t lrow = (uint32_t)((dd >> 6) * 64 + key);
                uint32_t off = lrow * 128 + (dd & 63) * 2;
                uint32_t sw = off ^ ((off >> 3) & 0x70);
                LDSM4(bh, sb + sw);
                LDSM4(bl, sb + 16384u + sw);
#pragma unroll
                for (int t = 0; t < 2; t++) {
                    MMA16816(s[np * 2 + t], ah, bh[2 * t], bh[2 * t + 1]);
                    MMA16816(s[np * 2 + t], ah, bl[2 * t], bl[2 * t + 1]);
                    MMA16816(s[np * 2 + t], al, bh[2 * t], bh[2 * t + 1]);
                }
            }
        }

#pragma unroll
        for (int nt = 0; nt < 8; nt++) {
            const int kc = kb + nt * 8 + tig * 2;
#pragma unroll
            for (int jj = 0; jj < 4; jj++) {
                const int q = q0 + wq + gid + ((jj >> 1) << 3);
                const int k = kc + (jj & 1);
                const bool valid = (k <= q) && ((q - k < WIN) || (k < SINK));
                s[nt][jj] = valid ? s[nt][jj] * scale : -1e30f;
            }
        }

        float tm0 = -1e30f, tm1 = -1e30f;
#pragma unroll
        for (int nt = 0; nt < 8; nt++) {
            tm0 = fmaxf(tm0, fmaxf(s[nt][0], s[nt][1]));
            tm1 = fmaxf(tm1, fmaxf(s[nt][2], s[nt][3]));
        }
        tm0 = fmaxf(tm0, __shfl_xor_sync(0xffffffffu, tm0, 1));
        tm0 = fmaxf(tm0, __shfl_xor_sync(0xffffffffu, tm0, 2));
        tm1 = fmaxf(tm1, __shfl_xor_sync(0xffffffffu, tm1, 1));
        tm1 = fmaxf(tm1, __shfl_xor_sync(0xffffffffu, tm1, 2));
        const float m0n = fmaxf(m0r, tm0), m1n = fmaxf(m1r, tm1);
        const float al0 = __expf(m0r - m0n), al1 = __expf(m1r - m1n);
        m0r = m0n; m1r = m1n;

        float rs0 = 0.0f, rs1 = 0.0f;
#pragma unroll
        for (int nt = 0; nt < 8; nt++) {
            float p0 = __expf(s[nt][0] - m0n);
            float p1 = __expf(s[nt][1] - m0n);
            float p2 = __expf(s[nt][2] - m1n);
            float p3 = __expf(s[nt][3] - m1n);
            s[nt][0] = p0; s[nt][1] = p1; s[nt][2] = p2; s[nt][3] = p3;
            rs0 += p0 + p1; rs1 += p2 + p3;
        }
        rs0 += __shfl_xor_sync(0xffffffffu, rs0, 1);
        rs0 += __shfl_xor_sync(0xffffffffu, rs0, 2);
        rs1 += __shfl_xor_sync(0xffffffffu, rs1, 1);
        rs1 += __shfl_xor_sync(0xffffffffu, rs1, 2);
        l0r = l0r * al0 + rs0;
        l1r = l1r * al1 + rs1;

#pragma unroll
        for (int dt = 0; dt < 16; dt++) {
            o[dt][0] *= al0; o[dt][1] *= al0;
            o[dt][2] *= al1; o[dt][3] *= al1;
        }

        uint32_t ph[4][4], pl[4][4];
#pragma unroll
        for (int ks = 0; ks < 4; ks++) {
            split2(s[2 * ks][0],     s[2 * ks][1],     ph[ks][0], pl[ks][0]);
            split2(s[2 * ks][2],     s[2 * ks][3],     ph[ks][1], pl[ks][1]);
            split2(s[2 * ks + 1][0], s[2 * ks + 1][1], ph[ks][2], pl[ks][2]);
            split2(s[2 * ks + 1][2], s[2 * ks + 1][3], ph[ks][3], pl[ks][3]);
        }

#pragma unroll
        for (int np = 0; np < 8; np++) {
#pragma unroll
            for (int ks = 0; ks < 4; ks++) {
                uint32_t vh[4], vl[4];
                int key = ks * 16 + (lane & 7) + ((lane >> 3) & 1) * 8;
                int dd = np * 16 + ((lane >> 4) << 3);
                uint32_t lrow = (uint32_t)((dd >> 6) * 64 + key);
                uint32_t off = lrow * 128 + (dd & 63) * 2;
                uint32_t sw = off ^ ((off >> 3) & 0x70);
                LDSM4T(vh, sb + 32768u + sw);
                LDSM4T(vl, sb + 49152u + sw);
#pragma unroll
                for (int t = 0; t < 2; t++) {
                    MMA16816(o[np * 2 + t], ph[ks], vh[2 * t], vh[2 * t + 1]);
                    MMA16816(o[np * 2 + t], ph[ks], vl[2 * t], vl[2 * t + 1]);
                    MMA16816(o[np * 2 + t], pl[ks], vh[2 * t], vh[2 * t + 1]);
                }
            }
        }
        __syncthreads();
    }

    const float inv0 = 1.0f / l0r, inv1 = 1.0f / l1r;
    const size_t ob = ((size_t)(b * S_LEN + q0 + wq)) * D_DIM + h * HDIM;
#pragma unroll
    for (int dt = 0; dt < 16; dt++) {
        const int dd = dt * 8 + tig * 2;
        uint32_t hh, ll;
        split2(o[dt][0] * inv0, o[dt][1] * inv0, hh, ll);
        *(uint32_t*)(Oh_g + ob + (size_t)gid * D_DIM + dd) = hh;
        *(uint32_t*)(Ol_g + ob + (size_t)gid * D_DIM + dd) = ll;
        split2(o[dt][2] * inv1, o[dt][3] * inv1, hh, ll);
        *(uint32_t*)(Oh_g + ob + (size_t)(gid + 8) * D_DIM + dd) = hh;
        *(uint32_t*)(Ol_g + ob + (size_t)(gid + 8) * D_DIM + dd) = ll;
    }
}

// ---------------- launch ------------------------------------------------------
extern "C" void kernel_launch(void* const* d_in, const int* in_sizes, int n_in,
                              void* d_out, int out_size)
{
    const float* x   = (const float*)d_in[0];
    const float* Wq  = (const float*)d_in[1];
    const float* Wkv = (const float*)d_in[2];
    const float* Wk  = (const float*)d_in[3];
    const float* Wv  = (const float*)d_in[4];
    const float* Wo  = (const float*)d_in[5];
    float* out = (float*)d_out;

    __nv_bfloat16 *Xh, *Xl, *KVh, *KVl, *Qh, *Ql, *Kh, *Kl, *Vh, *Vl, *AOh, *AOl;
    __nv_bfloat16 *W1h, *W1l, *W2h, *W2l, *WoTh, *WoTl;
    cudaGetSymbolAddress((void**)&Xh, g_Xh);   cudaGetSymbolAddress((void**)&Xl, g_Xl);
    cudaGetSymbolAddress((void**)&KVh, g_KVh); cudaGetSymbolAddress((void**)&KVl, g_KVl);
    cudaGetSymbolAddress((void**)&Qh, g_Qh);   cudaGetSymbolAddress((void**)&Ql, g_Ql);
    cudaGetSymbolAddress((void**)&Kh, g_Kh);   cudaGetSymbolAddress((void**)&Kl, g_Kl);
    cudaGetSymbolAddress((void**)&Vh, g_Vh);   cudaGetSymbolAddress((void**)&Vl, g_Vl);
    cudaGetSymbolAddress((void**)&AOh, g_AOh); cudaGetSymbolAddress((void**)&AOl, g_AOl);
    cudaGetSymbolAddress((void**)&W1h, g_W1h); cudaGetSymbolAddress((void**)&W1l, g_W1l);
    cudaGetSymbolAddress((void**)&W2h, g_W2h); cudaGetSymbolAddress((void**)&W2l, g_W2l);
    cudaGetSymbolAddress((void**)&WoTh, g_WoTh); cudaGetSymbolAddress((void**)&WoTl, g_WoTl);

    cudaFuncSetAttribute(mm_kernel,   cudaFuncAttributeMaxDynamicSharedMemorySize, MM_SMEM_BYTES);
    cudaFuncSetAttribute(attn_kernel, cudaFuncAttributeMaxDynamicSharedMemorySize, A_SMEM_BYTES);

    const dim3 tb(32, 8);
    // --- conversions (weights into merged buffers) ---
    {
        int n4 = MROWS * D_DIM / 4;
        split_kernel<<<(n4 + 255) / 256, 256>>>((const float4*)x, (__nv_bfloat162*)Xh, (__nv_bfloat162*)Xl, n4);
    }
    tsplit_kernel<<<dim3(D_DIM / 32, D_DIM / 32), tb>>>(Wq,  W1h, W1l, D_DIM, D_DIM);
    tsplit_kernel<<<dim3(L_DIM / 32, D_DIM / 32), tb>>>(Wkv, W1h + (size_t)D_DIM * D_DIM,
                                                        W1l + (size_t)D_DIM * D_DIM, D_DIM, L_DIM);
    tsplit_kernel<<<dim3(D_DIM / 32, L_DIM / 32), tb>>>(Wk,  W2h, W2l, L_DIM, D_DIM);
    tsplit_kernel<<<dim3(D_DIM / 32, L_DIM / 32), tb>>>(Wv,  W2h + (size_t)D_DIM * L_DIM,
                                                        W2l + (size_t)D_DIM * L_DIM, L_DIM, D_DIM);
    tsplit_kernel<<<dim3(D_DIM / 32, D_DIM / 32), tb>>>(Wo,  WoTh, WoTl, D_DIM, D_DIM);

    // --- [Q | KV] = X @ [Wq | Wkv]  (N = 2560, split at 2048) ---
    mm_kernel<<<dim3((D_DIM + L_DIM) / 128, MROWS / 128), 256, MM_SMEM_BYTES>>>(
        Xh, Xl, W1h, W1l, nullptr,
        Qh, Ql, D_DIM, KVh, KVl, L_DIM, D_DIM, D_DIM, 1);

    // --- [K | V] = KV @ [Wk | Wv]  (N = 4096, split at 2048) ---
    mm_kernel<<<dim3((2 * D_DIM) / 128, MROWS / 128), 256, MM_SMEM_BYTES>>>(
        KVh, KVl, W2h, W2l, nullptr,
        Kh, Kl, D_DIM, Vh, Vl, D_DIM, D_DIM, L_DIM, 1);

    // --- attention (HMMA, bf16-split in/out) ---
    attn_kernel<<<dim3(S_LEN / AQT, NHEADS, B_SZ), 256, A_SMEM_BYTES>>>(
        Qh, Ql, Kh, Kl, Vh, Vl, AOh, AOl);

    // --- out = AO @ Wo (fp32 out) ---
    mm_kernel<<<dim3(D_DIM / 128, MROWS / 128), 256, MM_SMEM_BYTES>>>(
        AOh, AOl, WoTh, WoTl, out,
        nullptr, nullptr, D_DIM, nullptr, nullptr, 0, 1 << 30, D_DIM, 0);
}